// round 9
// baseline (speedup 1.0000x reference)
#include <cuda_runtime.h>
#include <cuda_fp16.h>

// Problem constants
#define Bn     8192
#define Tb     32        // batch rows per block (fp16 chain in smem)
#define F0n    2048
#define En     512
#define OUTn   2048
#define Wn     3584      // F0 + 3*E
#define NNZ_E  8192
#define NNZ_M  16384
#define NBLK   (Bn / Tb) // 256
#define NTHR   1024      // 32 warps

// Entry storage: rows padded to multiples of 4 (zero pads), col pre-scaled *64.
#define EB0 0
#define EB1 16384
#define EB2 32768
#define EBM 49152
#define ENT_TOT 73728    // 3*16384 + 24576
__device__ int2 g_ent[ENT_TOT];
__device__ int  g_ptr[4 * 2049];

// ---------------------------------------------------------------------------
__global__ void zero_ent_k() {
    int i = blockIdx.x * blockDim.x + threadIdx.x;
    if (i < ENT_TOT) g_ent[i] = make_int2(0, 0);
}

// ---------------------------------------------------------------------------
// CSR build, pad-4, col pre-scaled to byte offset (col*64).
// ---------------------------------------------------------------------------
#define BLD 512
__global__ void build_k(const int* __restrict__ r0, const int* __restrict__ c0, const float* __restrict__ v0,
                        const int* __restrict__ r1, const int* __restrict__ c1, const float* __restrict__ v1,
                        const int* __restrict__ r2, const int* __restrict__ c2, const float* __restrict__ v2,
                        const int* __restrict__ rm, const int* __restrict__ cm, const float* __restrict__ vm) {
    __shared__ int cnt[2048];
    __shared__ int cur[2048];
    __shared__ int part[BLD];
    int w = blockIdx.x;
    int t = threadIdx.x;

    const int*   rows = (w == 0) ? r0 : (w == 1) ? r1 : (w == 2) ? r2 : rm;
    const int*   cols = (w == 0) ? c0 : (w == 1) ? c1 : (w == 2) ? c2 : cm;
    const float* vals = (w == 0) ? v0 : (w == 1) ? v1 : (w == 2) ? v2 : vm;
    int nrows = (w < 3) ? En : OUTn;
    int nnz   = (w < 3) ? NNZ_E : NNZ_M;
    int ebase = (w == 0) ? EB0 : (w == 1) ? EB1 : (w == 2) ? EB2 : EBM;
    int per   = nrows / BLD;             // 1 or 4

    for (int i = t; i < 2048; i += BLD) cnt[i] = 0;
    __syncthreads();
    for (int k = t; k < nnz; k += BLD) atomicAdd(&cnt[rows[k]], 1);
    __syncthreads();

    int pad[4];
    int sum = 0;
    for (int j = 0; j < per; j++) {
        pad[j] = (cnt[t * per + j] + 3) & ~3;
        sum += pad[j];
    }
    part[t] = sum;
    __syncthreads();
    for (int off = 1; off < BLD; off <<= 1) {
        int v = (t >= off) ? part[t - off] : 0;
        __syncthreads();
        part[t] += v;
        __syncthreads();
    }
    int run = part[t] - sum;
    for (int j = 0; j < per; j++) {
        int i = t * per + j;
        g_ptr[w * 2049 + i] = run;
        cur[i] = run;
        run += pad[j];
    }
    if (t == BLD - 1) g_ptr[w * 2049 + nrows] = part[BLD - 1];
    __syncthreads();

    for (int k = t; k < nnz; k += BLD) {
        int p = atomicAdd(&cur[rows[k]], 1);
        g_ent[ebase + p] = make_int2(cols[k] * 64, __float_as_int(vals[k]));
    }
}

// ---------------------------------------------------------------------------
// Stream-split row accumulator. Lane = (s = lane>>3, q = lane&7).
// Entries of the row split 4 ways (stride-4, pad-4 -> equal counts n).
// hq = byte ptr to sh2 + q*8; each entry: LDS.64 (2 half2 = 4 batch).
// A = batches (4q,4q+1), B = (4q+2,4q+3), partial over stream s.
// ---------------------------------------------------------------------------
__device__ __forceinline__ void acc_row(const int2* __restrict__ ent,
                                        int S, int n, const char* hq, int s,
                                        float2& A, float2& B) {
    float2 a = make_float2(0.f, 0.f), b = make_float2(0.f, 0.f);
    int idx = S + s;
    int i = 0;
    for (; i + 2 <= n; i += 2) {
        int2 e0 = __ldg(ent + idx);
        int2 e1 = __ldg(ent + idx + 4);
        idx += 8;
        uint2 w0 = *reinterpret_cast<const uint2*>(hq + e0.x);
        uint2 w1 = *reinterpret_cast<const uint2*>(hq + e1.x);
        float v0 = __int_as_float(e0.y);
        float v1 = __int_as_float(e1.y);
        float2 h0 = __half22float2(*reinterpret_cast<const __half2*>(&w0.x));
        float2 h1 = __half22float2(*reinterpret_cast<const __half2*>(&w0.y));
        float2 h2 = __half22float2(*reinterpret_cast<const __half2*>(&w1.x));
        float2 h3 = __half22float2(*reinterpret_cast<const __half2*>(&w1.y));
        a.x += v0 * h0.x; a.y += v0 * h0.y;
        b.x += v0 * h1.x; b.y += v0 * h1.y;
        a.x += v1 * h2.x; a.y += v1 * h2.y;
        b.x += v1 * h3.x; b.y += v1 * h3.y;
    }
    if (i < n) {
        int2 e0 = __ldg(ent + idx);
        uint2 w0 = *reinterpret_cast<const uint2*>(hq + e0.x);
        float v0 = __int_as_float(e0.y);
        float2 h0 = __half22float2(*reinterpret_cast<const __half2*>(&w0.x));
        float2 h1 = __half22float2(*reinterpret_cast<const __half2*>(&w0.y));
        a.x += v0 * h0.x; a.y += v0 * h0.y;
        b.x += v0 * h1.x; b.y += v0 * h1.y;
    }
    A = a; B = b;
}

#define RED4(A, B)                                                   \
    A.x += __shfl_xor_sync(0xffffffffu, A.x, 8);                     \
    A.y += __shfl_xor_sync(0xffffffffu, A.y, 8);                     \
    B.x += __shfl_xor_sync(0xffffffffu, B.x, 8);                     \
    B.y += __shfl_xor_sync(0xffffffffu, B.y, 8);                     \
    A.x += __shfl_xor_sync(0xffffffffu, A.x, 16);                    \
    A.y += __shfl_xor_sync(0xffffffffu, A.y, 16);                    \
    B.x += __shfl_xor_sync(0xffffffffu, B.x, 16);                    \
    B.y += __shfl_xor_sync(0xffffffffu, B.y, 16);

// ---------------------------------------------------------------------------
// Fused chain kernel, v7: feature-major half2 h[col][16] (64B per col).
// ---------------------------------------------------------------------------
#define SMEM_BYTES (Wn * 16 * 4)    // 229376

__global__ void __launch_bounds__(NTHR, 1) fused_k(const float* __restrict__ x,
                                                   float* __restrict__ out) {
    extern __shared__ __half2 sh2[];

    int t    = threadIdx.x;
    int wid  = t >> 5;                  // 0..31
    int lane = t & 31;
    int s    = lane >> 3;               // stream 0..3
    int q    = lane & 7;                // batch quad 0..7
    int b0   = blockIdx.x * Tb;
    const char* hq = reinterpret_cast<const char*>(sh2) + q * 8;

    // ---- x load: staged transpose through the unused embed region ----
    {
        float* stage = reinterpret_cast<float*>(sh2 + (size_t)F0n * 16);
        int p  = t & 15;
        int j0 = t >> 4;
        for (int c = 0; c < 4; c++) {
            for (int i = t; i < Tb * 512; i += NTHR) {
                int bb = i >> 9, f = i & 511;
                stage[bb * 515 + f] = x[(size_t)(b0 + bb) * F0n + c * 512 + f];
            }
            __syncthreads();
            for (int jj = j0; jj < 512; jj += 64) {
                float lo = stage[(2 * p)     * 515 + jj];
                float hi = stage[(2 * p + 1) * 515 + jj];
                sh2[(size_t)(c * 512 + jj) * 16 + p] = __floats2half2_rn(lo, hi);
            }
            __syncthreads();
        }
    }

    // ---- three embed levels: 16 rows per warp ----
    for (int lev = 0; lev < 3; lev++) {
        int fo = F0n + lev * En;
        const int*  lptr = g_ptr + lev * 2049;
        const int2* ent  = g_ent + ((lev == 0) ? EB0 : (lev == 1) ? EB1 : EB2);
#pragma unroll 1
        for (int pr = 0; pr < 16; pr++) {
            int r = wid * 16 + pr;
            int S = __ldg(lptr + r);
            int n = (__ldg(lptr + r + 1) - S) >> 2;
            float2 A, B;
            acc_row(ent, S, n, hq, s, A, B);
            RED4(A, B);
            if (lane < 8) {              // stream 0 stores
                __half2* dst = sh2 + (size_t)(fo + r) * 16 + 2 * q;
                dst[0] = __floats2half2_rn(A.x, A.y);
                dst[1] = __floats2half2_rn(B.x, B.y);
            }
        }
        __syncthreads();
    }

    // ---- MAIN: warp owns 64 rows; 8-row register banks; no barriers ----
    const int*  mptr = g_ptr + 3 * 2049;
    const int2* ment = g_ent + EBM;
    int bmine = 4 * q + s;               // this lane's output batch row
    float* outp = out + (size_t)(b0 + bmine) * OUTn;
#pragma unroll 1
    for (int grp = 0; grp < 8; grp++) {
        int rb = wid * 64 + grp * 8;
        float a8[8];
#pragma unroll
        for (int j = 0; j < 8; j++) {
            int r = rb + j;
            int S = __ldg(mptr + r);
            int n = (__ldg(mptr + r + 1) - S) >> 2;
            float2 A, B;
            acc_row(ment, S, n, hq, s, A, B);
            RED4(A, B);
            a8[j] = (s == 0) ? A.x : (s == 1) ? A.y : (s == 2) ? B.x : B.y;
        }
        float4* o4 = reinterpret_cast<float4*>(outp + rb);
        o4[0] = make_float4(a8[0], a8[1], a8[2], a8[3]);
        o4[1] = make_float4(a8[4], a8[5], a8[6], a8[7]);
    }
}

// ---------------------------------------------------------------------------
// Launch
// ---------------------------------------------------------------------------
extern "C" void kernel_launch(void* const* d_in, const int* in_sizes, int n_in,
                              void* d_out, int out_size) {
    const float* x   = (const float*)d_in[0];
    const int*   er0 = (const int*)d_in[1];
    const int*   ec0 = (const int*)d_in[2];
    const float* ev0 = (const float*)d_in[3];
    const int*   er1 = (const int*)d_in[4];
    const int*   ec1 = (const int*)d_in[5];
    const float* ev1 = (const float*)d_in[6];
    const int*   er2 = (const int*)d_in[7];
    const int*   ec2 = (const int*)d_in[8];
    const float* ev2 = (const float*)d_in[9];
    const int*   mr  = (const int*)d_in[10];
    const int*   mc  = (const int*)d_in[11];
    const float* mv  = (const float*)d_in[12];
    float* out = (float*)d_out;

    static int attr_done = 0;
    if (!attr_done) {
        cudaFuncSetAttribute(fused_k, cudaFuncAttributeMaxDynamicSharedMemorySize,
                             SMEM_BYTES);
        attr_done = 1;
    }

    zero_ent_k<<<(ENT_TOT + 255) / 256, 256>>>();
    build_k<<<4, BLD>>>(er0, ec0, ev0, er1, ec1, ev1, er2, ec2, ev2, mr, mc, mv);
    fused_k<<<NBLK, NTHR, SMEM_BYTES>>>(x, out);
}

// round 10
// speedup vs baseline: 1.0808x; 1.0808x over previous
#include <cuda_runtime.h>
#include <cuda_fp16.h>

// Problem constants
#define Bn     8192
#define Tb     32        // batch rows per block (fp16 chain in smem)
#define F0n    2048
#define En     512
#define OUTn   2048
#define Wn     3584      // F0 + 3*E
#define NNZ_E  8192
#define NNZ_M  16384
#define NBLK   (Bn / Tb) // 256
#define NTHR   1024      // 32 warps

// ---------------------------------------------------------------------------
// Device scratch (no allocation allowed)
// ---------------------------------------------------------------------------
__device__ int  g_ptr[4 * 2049];
__device__ int2 g_ent[4 * 16384];   // packed {col*64 (byte off), float_bits(val)}

// ---------------------------------------------------------------------------
// CSR build: one block per weight. Columns pre-scaled to byte offsets (*64).
// ---------------------------------------------------------------------------
#define BLD 512
__global__ void build_k(const int* __restrict__ r0, const int* __restrict__ c0, const float* __restrict__ v0,
                        const int* __restrict__ r1, const int* __restrict__ c1, const float* __restrict__ v1,
                        const int* __restrict__ r2, const int* __restrict__ c2, const float* __restrict__ v2,
                        const int* __restrict__ rm, const int* __restrict__ cm, const float* __restrict__ vm) {
    __shared__ int cnt[2048];
    __shared__ int cur[2048];
    __shared__ int part[BLD];
    int w = blockIdx.x;
    int t = threadIdx.x;

    const int*   rows = (w == 0) ? r0 : (w == 1) ? r1 : (w == 2) ? r2 : rm;
    const int*   cols = (w == 0) ? c0 : (w == 1) ? c1 : (w == 2) ? c2 : cm;
    const float* vals = (w == 0) ? v0 : (w == 1) ? v1 : (w == 2) ? v2 : vm;
    int nrows = (w < 3) ? En : OUTn;
    int nnz   = (w < 3) ? NNZ_E : NNZ_M;
    int per   = nrows / BLD;             // 1 or 4

    for (int i = t; i < 2048; i += BLD) cnt[i] = 0;
    __syncthreads();
    for (int k = t; k < nnz; k += BLD) atomicAdd(&cnt[rows[k]], 1);
    __syncthreads();

    int sum = 0;
    for (int j = 0; j < per; j++) sum += cnt[t * per + j];
    part[t] = sum;
    __syncthreads();
    for (int off = 1; off < BLD; off <<= 1) {
        int v = (t >= off) ? part[t - off] : 0;
        __syncthreads();
        part[t] += v;
        __syncthreads();
    }
    int run = part[t] - sum;
    for (int j = 0; j < per; j++) {
        int i = t * per + j;
        g_ptr[w * 2049 + i] = run;
        cur[i] = run;
        run += cnt[i];
    }
    if (t == BLD - 1) g_ptr[w * 2049 + nrows] = part[BLD - 1];
    __syncthreads();

    for (int k = t; k < nnz; k += BLD) {
        int p = atomicAdd(&cur[rows[k]], 1);
        g_ent[w * 16384 + p] = make_int2(cols[k] * 64, __float_as_int(vals[k]));
    }
}

// ---------------------------------------------------------------------------
// Dual-row accumulator, feature-major addressing: hb = smem byte base + bp*4.
// Half kh walks its parity of each row's entry list. Entry.x is a byte offset.
// ---------------------------------------------------------------------------
__device__ __forceinline__ void row_pair_f(const int2* __restrict__ ent,
                                           int sA, int eA, int sB, int eB,
                                           const char* __restrict__ hb, int kh,
                                           float2& oA, float2& oB) {
    float2 a = make_float2(0.f, 0.f), c = make_float2(0.f, 0.f);
    int kA = sA + kh, kB = sB + kh;
    while (kA + 6 < eA && kB + 6 < eB) {
        int2 x0 = __ldg(ent + kA);
        int2 x1 = __ldg(ent + kA + 2);
        int2 x2 = __ldg(ent + kA + 4);
        int2 x3 = __ldg(ent + kA + 6);
        int2 y0 = __ldg(ent + kB);
        int2 y1 = __ldg(ent + kB + 2);
        int2 y2 = __ldg(ent + kB + 4);
        int2 y3 = __ldg(ent + kB + 6);
        float2 h0 = __half22float2(*reinterpret_cast<const __half2*>(hb + x0.x));
        float2 g0 = __half22float2(*reinterpret_cast<const __half2*>(hb + y0.x));
        float2 h1 = __half22float2(*reinterpret_cast<const __half2*>(hb + x1.x));
        float2 g1 = __half22float2(*reinterpret_cast<const __half2*>(hb + y1.x));
        float2 h2 = __half22float2(*reinterpret_cast<const __half2*>(hb + x2.x));
        float2 g2 = __half22float2(*reinterpret_cast<const __half2*>(hb + y2.x));
        float2 h3 = __half22float2(*reinterpret_cast<const __half2*>(hb + x3.x));
        float2 g3 = __half22float2(*reinterpret_cast<const __half2*>(hb + y3.x));
        float v0 = __int_as_float(x0.y), w0 = __int_as_float(y0.y);
        float v1 = __int_as_float(x1.y), w1 = __int_as_float(y1.y);
        float v2 = __int_as_float(x2.y), w2 = __int_as_float(y2.y);
        float v3 = __int_as_float(x3.y), w3 = __int_as_float(y3.y);
        a.x += v0 * h0.x; a.y += v0 * h0.y;
        c.x += w0 * g0.x; c.y += w0 * g0.y;
        a.x += v1 * h1.x; a.y += v1 * h1.y;
        c.x += w1 * g1.x; c.y += w1 * g1.y;
        a.x += v2 * h2.x; a.y += v2 * h2.y;
        c.x += w2 * g2.x; c.y += w2 * g2.y;
        a.x += v3 * h3.x; a.y += v3 * h3.y;
        c.x += w3 * g3.x; c.y += w3 * g3.y;
        kA += 8; kB += 8;
    }
    while (kA + 6 < eA) {
        int2 x0 = __ldg(ent + kA);
        int2 x1 = __ldg(ent + kA + 2);
        int2 x2 = __ldg(ent + kA + 4);
        int2 x3 = __ldg(ent + kA + 6);
        float2 h0 = __half22float2(*reinterpret_cast<const __half2*>(hb + x0.x));
        float2 h1 = __half22float2(*reinterpret_cast<const __half2*>(hb + x1.x));
        float2 h2 = __half22float2(*reinterpret_cast<const __half2*>(hb + x2.x));
        float2 h3 = __half22float2(*reinterpret_cast<const __half2*>(hb + x3.x));
        a.x += __int_as_float(x0.y) * h0.x; a.y += __int_as_float(x0.y) * h0.y;
        a.x += __int_as_float(x1.y) * h1.x; a.y += __int_as_float(x1.y) * h1.y;
        a.x += __int_as_float(x2.y) * h2.x; a.y += __int_as_float(x2.y) * h2.y;
        a.x += __int_as_float(x3.y) * h3.x; a.y += __int_as_float(x3.y) * h3.y;
        kA += 8;
    }
    while (kB + 6 < eB) {
        int2 y0 = __ldg(ent + kB);
        int2 y1 = __ldg(ent + kB + 2);
        int2 y2 = __ldg(ent + kB + 4);
        int2 y3 = __ldg(ent + kB + 6);
        float2 g0 = __half22float2(*reinterpret_cast<const __half2*>(hb + y0.x));
        float2 g1 = __half22float2(*reinterpret_cast<const __half2*>(hb + y1.x));
        float2 g2 = __half22float2(*reinterpret_cast<const __half2*>(hb + y2.x));
        float2 g3 = __half22float2(*reinterpret_cast<const __half2*>(hb + y3.x));
        c.x += __int_as_float(y0.y) * g0.x; c.y += __int_as_float(y0.y) * g0.y;
        c.x += __int_as_float(y1.y) * g1.x; c.y += __int_as_float(y1.y) * g1.y;
        c.x += __int_as_float(y2.y) * g2.x; c.y += __int_as_float(y2.y) * g2.y;
        c.x += __int_as_float(y3.y) * g3.x; c.y += __int_as_float(y3.y) * g3.y;
        kB += 8;
    }
    for (; kA < eA; kA += 2) {
        int2 x = __ldg(ent + kA);
        float2 h = __half22float2(*reinterpret_cast<const __half2*>(hb + x.x));
        a.x += __int_as_float(x.y) * h.x; a.y += __int_as_float(x.y) * h.y;
    }
    for (; kB < eB; kB += 2) {
        int2 y = __ldg(ent + kB);
        float2 g = __half22float2(*reinterpret_cast<const __half2*>(hb + y.x));
        c.x += __int_as_float(y.y) * g.x; c.y += __int_as_float(y.y) * g.y;
    }
    oA = a; oB = c;
}

// ---------------------------------------------------------------------------
// Fused chain kernel, v8: feature-major half2 h2[col][16] (64B per column),
// R8's lane decomposition: bp = lane&15 (batch pair), kh = lane>>4 (parity).
// Address = per-lane byte base + pre-scaled entry offset (1 IADD, no XOR).
// ---------------------------------------------------------------------------
#define SMEM_BYTES (Wn * 16 * 4)    // 229376

__global__ void __launch_bounds__(NTHR, 1) fused_k(const float* __restrict__ x,
                                                   float* __restrict__ out) {
    extern __shared__ __half2 sh2[];

    int t    = threadIdx.x;
    int wid  = t >> 5;                  // 0..31
    int lane = t & 31;
    int kh   = lane >> 4;               // entry-stream half
    int bp   = lane & 15;               // batch-pair index
    int b0   = blockIdx.x * Tb;
    const char* hb = reinterpret_cast<const char*>(sh2) + bp * 4;

    // ---- x load: staged transpose through the unused embed col region ----
    {
        float* stage = reinterpret_cast<float*>(sh2 + (size_t)F0n * 16);
        int p  = t & 15;
        int j0 = t >> 4;
        for (int c = 0; c < 4; c++) {
            for (int i = t; i < Tb * 512; i += NTHR) {
                int bb = i >> 9, f = i & 511;
                stage[bb * 515 + f] = x[(size_t)(b0 + bb) * F0n + c * 512 + f];
            }
            __syncthreads();
            for (int jj = j0; jj < 512; jj += 64) {
                float lo = stage[(2 * p)     * 515 + jj];
                float hi = stage[(2 * p + 1) * 515 + jj];
                sh2[(size_t)(c * 512 + jj) * 16 + p] = __floats2half2_rn(lo, hi);
            }
            __syncthreads();
        }
    }

    // ---- three embed levels: 16 rows/warp as 8 pairs ----
    for (int lev = 0; lev < 3; lev++) {
        int fo = F0n + lev * En;
        const int*  lptr = g_ptr + lev * 2049;
        const int2* ent  = g_ent + lev * 16384;
#pragma unroll 1
        for (int pr = 0; pr < 8; pr++) {
            int r  = wid * 16 + pr * 2;
            int sA = __ldg(lptr + r);
            int sB = __ldg(lptr + r + 1);
            int eB = __ldg(lptr + r + 2);
            float2 vA, vB;
            row_pair_f(ent, sA, sB, sB, eB, hb, kh, vA, vB);
            vA.x += __shfl_xor_sync(0xffffffffu, vA.x, 16);
            vA.y += __shfl_xor_sync(0xffffffffu, vA.y, 16);
            vB.x += __shfl_xor_sync(0xffffffffu, vB.x, 16);
            vB.y += __shfl_xor_sync(0xffffffffu, vB.y, 16);
            // kh=0 stores row r, kh=1 stores row r+1 (both halves busy)
            float2 vm = kh ? vB : vA;
            sh2[(size_t)(fo + r + kh) * 16 + bp] = __floats2half2_rn(vm.x, vm.y);
        }
        __syncthreads();
    }

    // ---- MAIN: warp owns 64 rows in 8 groups of 8; every lane writes its
    //      own batch row (2bp + kh); no block barriers ----
    const int*  mptr = g_ptr + 3 * 2049;
    const int2* ment = g_ent + 3 * 16384;
    float* outp = out + (size_t)(b0 + 2 * bp + kh) * OUTn;
#pragma unroll 1
    for (int grp = 0; grp < 8; grp++) {
        int rb = wid * 64 + grp * 8;
        float a8[8];
#pragma unroll
        for (int jp = 0; jp < 4; jp++) {
            int r  = rb + jp * 2;
            int sA = __ldg(mptr + r);
            int sB = __ldg(mptr + r + 1);
            int eB = __ldg(mptr + r + 2);
            float2 vA, vB;
            row_pair_f(ment, sA, sB, sB, eB, hb, kh, vA, vB);
            vA.x += __shfl_xor_sync(0xffffffffu, vA.x, 16);
            vA.y += __shfl_xor_sync(0xffffffffu, vA.y, 16);
            vB.x += __shfl_xor_sync(0xffffffffu, vB.x, 16);
            vB.y += __shfl_xor_sync(0xffffffffu, vB.y, 16);
            a8[jp * 2]     = kh ? vA.y : vA.x;
            a8[jp * 2 + 1] = kh ? vB.y : vB.x;
        }
        float4* o4 = reinterpret_cast<float4*>(outp + rb);
        o4[0] = make_float4(a8[0], a8[1], a8[2], a8[3]);
        o4[1] = make_float4(a8[4], a8[5], a8[6], a8[7]);
    }
}

// ---------------------------------------------------------------------------
// Launch
// ---------------------------------------------------------------------------
extern "C" void kernel_launch(void* const* d_in, const int* in_sizes, int n_in,
                              void* d_out, int out_size) {
    const float* x   = (const float*)d_in[0];
    const int*   er0 = (const int*)d_in[1];
    const int*   ec0 = (const int*)d_in[2];
    const float* ev0 = (const float*)d_in[3];
    const int*   er1 = (const int*)d_in[4];
    const int*   ec1 = (const int*)d_in[5];
    const float* ev1 = (const float*)d_in[6];
    const int*   er2 = (const int*)d_in[7];
    const int*   ec2 = (const int*)d_in[8];
    const float* ev2 = (const float*)d_in[9];
    const int*   mr  = (const int*)d_in[10];
    const int*   mc  = (const int*)d_in[11];
    const float* mv  = (const float*)d_in[12];
    float* out = (float*)d_out;

    static int attr_done = 0;
    if (!attr_done) {
        cudaFuncSetAttribute(fused_k, cudaFuncAttributeMaxDynamicSharedMemorySize,
                             SMEM_BYTES);
        attr_done = 1;
    }

    build_k<<<4, BLD>>>(er0, ec0, ev0, er1, ec1, ev1, er2, ec2, ev2, mr, mc, mv);
    fused_k<<<NBLK, NTHR, SMEM_BYTES>>>(x, out);
}